// round 11
// baseline (speedup 1.0000x reference)
#include <cuda_runtime.h>
#include <stdint.h>
#include <math.h>

#define B_N 2
#define S_N 2048
#define HID_N 2048
#define H_N 16
#define KV_N 4
#define QKB_N 64
#define VB_N 64
#define MTOT (B_N * S_N)

// ---- scratch (__device__ globals: allocation-free rule) ----
__device__ float g_qb[(size_t)MTOT * H_N * QKB_N];    // round(tanh(x@Wq))
__device__ float g_kb[(size_t)MTOT * KV_N * QKB_N];   // round(tanh(x@Wk))
__device__ float g_vp[(size_t)MTOT * KV_N * VB_N];    // round(sigm(x@Wv)-0.5)
__device__ float g_vpT[(size_t)B_N * KV_N * VB_N * S_N]; // V transposed [b][kv][vb][s]
__device__ float g_obd[(size_t)MTOT * H_N * VB_N];    // round((ctx-.5)*(e1-e0))
__device__ float g_cvec[HID_N];
__device__ float g_xr [(size_t)MTOT * HID_N];         // round(x)
__device__ float g_wqt[(size_t)(H_N * QKB_N) * HID_N];   // round(Wq^T) [N][K]
__device__ float g_wkt[(size_t)(KV_N * QKB_N) * HID_N];  // round(Wk^T)
__device__ float g_wvt[(size_t)(KV_N * VB_N) * HID_N];   // round(Wv^T)
__device__ float g_wot[(size_t)HID_N * (H_N * VB_N)];    // round(Wo^T)

// ---- helpers ----
__device__ __forceinline__ uint32_t smem_u32(const void* p) {
  return (uint32_t)__cvta_generic_to_shared(p);
}

__device__ __forceinline__ void cp16(uint32_t dst, const void* src) {
  asm volatile("cp.async.cg.shared.global [%0], [%1], 16;"
               : : "r"(dst), "l"(src) : "memory");
}

__device__ __forceinline__ void cp_commit() {
  asm volatile("cp.async.commit_group;" : : : "memory");
}

__device__ __forceinline__ void cp_waitg0() {
  asm volatile("cp.async.wait_group 0;" : : : "memory");
}
__device__ __forceinline__ void cp_waitg1() {
  asm volatile("cp.async.wait_group 1;" : : : "memory");
}

__device__ __forceinline__ uint32_t f2tf32(float v) {
  uint32_t r;
  asm("cvt.rna.tf32.f32 %0, %1;" : "=r"(r) : "f"(v));
  return r;
}

__device__ __forceinline__ float rnd_tf32(float v) {
  return __uint_as_float(f2tf32(v));
}

__device__ __forceinline__ void ldsm4(uint32_t* r, uint32_t a) {
  asm volatile("ldmatrix.sync.aligned.m8n8.x4.shared.b16 {%0,%1,%2,%3}, [%4];"
               : "=r"(r[0]), "=r"(r[1]), "=r"(r[2]), "=r"(r[3])
               : "r"(a));
}

__device__ __forceinline__ void mma_tf32(float* d, const uint32_t* a, const uint32_t* b) {
  asm volatile(
    "mma.sync.aligned.m16n8k8.row.col.f32.tf32.tf32.f32 "
    "{%0,%1,%2,%3}, {%4,%5,%6,%7}, {%8,%9}, {%0,%1,%2,%3};"
    : "+f"(d[0]), "+f"(d[1]), "+f"(d[2]), "+f"(d[3])
    : "r"(a[0]), "r"(a[1]), "r"(a[2]), "r"(a[3]), "r"(b[0]), "r"(b[1]));
}

// ---- fp32 -> tf32-rounded fp32 ----
__global__ void round_tf32_kernel(const float* __restrict__ in,
                                  float* __restrict__ out, int n4) {
  int i = blockIdx.x * blockDim.x + threadIdx.x;
  if (i < n4) {
    float4 v = ((const float4*)in)[i];
    v.x = rnd_tf32(v.x);
    v.y = rnd_tf32(v.y);
    v.z = rnd_tf32(v.z);
    v.w = rnd_tf32(v.w);
    ((float4*)out)[i] = v;
  }
}

// ---- transpose + round: out[n][k] = rnd(in[k][n]) ----
__global__ void transpose_round_kernel(const float* __restrict__ in,
                                       float* __restrict__ out, int K, int N) {
  __shared__ float t[32][33];
  const int tx = threadIdx.x & 31;
  const int ty = threadIdx.x >> 5;
  const int n0 = blockIdx.x * 32;
  const int k0 = blockIdx.y * 32;
#pragma unroll
  for (int i = 0; i < 4; ++i) {
    int k = k0 + ty + i * 8;
    t[ty + i * 8][tx] = in[(size_t)k * N + n0 + tx];
  }
  __syncthreads();
#pragma unroll
  for (int i = 0; i < 4; ++i) {
    int n = n0 + ty + i * 8;
    out[(size_t)n * K + k0 + tx] = rnd_tf32(t[tx][ty + i * 8]);
  }
}

// ---- V transpose: g_vp[b][s][n] -> g_vpT[b][n][s]  (n = kv*64+vb, 256 wide)
__global__ void transpose_v_kernel() {
  __shared__ float t[32][33];
  const int tx = threadIdx.x & 31;
  const int ty = threadIdx.x >> 5;
  const int n0 = blockIdx.x * 32;
  const int s0 = blockIdx.y * 32;
  const int b  = blockIdx.z;
#pragma unroll
  for (int i = 0; i < 4; ++i) {
    t[ty + i * 8][tx] = g_vp[((size_t)b * S_N + s0 + ty + i * 8) * (KV_N * VB_N) + n0 + tx];
  }
  __syncthreads();
#pragma unroll
  for (int i = 0; i < 4; ++i) {
    g_vpT[((size_t)b * (KV_N * VB_N) + n0 + ty + i * 8) * S_N + s0 + tx] = t[tx][ty + i * 8];
  }
}

// ---- cvec[n] = sum_k 0.5*(e0[k]+e1[k]) * Wo[k][n]; k-split x4 + reduce ----
__global__ void cvec_kernel(const float* __restrict__ e0, const float* __restrict__ e1,
                            const float* __restrict__ Wo) {
  __shared__ float part[4][64];
  const int tid = threadIdx.x;
  const int col = tid & 63;
  const int sl = tid >> 6;
  const int n = blockIdx.x * 64 + col;
  float s = 0.f;
  const int k0 = sl * 256;
  for (int k = k0; k < k0 + 256; ++k) {
    s = fmaf(0.5f * (e0[k] + e1[k]), Wo[(size_t)k * HID_N + n], s);
  }
  part[sl][col] = s;
  __syncthreads();
  if (sl == 0) {
    g_cvec[n] = part[0][col] + part[1][col] + part[2][col] + part[3][col];
  }
}

// ---------------------------------------------------------------------------
// TF32 GEMM (unchanged from R10): 128x128x32 tile, 3-stage cp.async ring,
// XOR-chunk swizzle, mma.m16n8k8 + ldmatrix.
// ---------------------------------------------------------------------------
#define STG_B 32768u
#define GEMM_DSMEM (3 * 32768)

__device__ __forceinline__ void g_prefetch(
    const float* __restrict__ A, const float* __restrict__ BT,
    uint32_t sA, int tid, int m0, int n0, int kt, int K) {
#pragma unroll
  for (int it = 0; it < 4; ++it) {
    int c = tid + it * 256;
    int r = c >> 3;
    int ch = c & 7;
    cp16(sA + r * 128 + ((uint32_t)(ch ^ (r & 7)) << 4),
         A + (size_t)(m0 + r) * K + kt * 32 + ch * 4);
  }
#pragma unroll
  for (int it = 0; it < 4; ++it) {
    int c = tid + it * 256;
    int r = c >> 3;
    int ch = c & 7;
    cp16(sA + 16384u + r * 128 + ((uint32_t)(ch ^ (r & 7)) << 4),
         BT + (size_t)(n0 + r) * K + kt * 32 + ch * 4);
  }
}

__device__ __forceinline__ void gemm_body(
    const float* __restrict__ A, const float* __restrict__ BT,
    float* __restrict__ C, int N, int K, int m0, int n0, int epi,
    const float* __restrict__ cvec) {
  extern __shared__ float gsm[];
  const int tid = threadIdx.x;
  const int wid = tid >> 5;
  const int lane = tid & 31;
  const int wm = wid & 3;
  const int wn = wid >> 2;
  const int lg = lane >> 2;
  const int lt = lane & 3;
  const int rA = lane & 15;
  const int hiA = lane >> 4;
  const int rB = ((lane >> 4) << 3) + (lane & 7);
  const int hiB = (lane >> 3) & 1;
  const uint32_t sbase = smem_u32(gsm);

  float acc[2][8][4];
#pragma unroll
  for (int i = 0; i < 2; ++i) {
#pragma unroll
    for (int j = 0; j < 8; ++j) {
#pragma unroll
      for (int t = 0; t < 4; ++t) { acc[i][j][t] = 0.f; }
    }
  }

  const int KT = K / 32;
  g_prefetch(A, BT, sbase + 0 * STG_B, tid, m0, n0, 0, K);
  cp_commit();
  g_prefetch(A, BT, sbase + 1 * STG_B, tid, m0, n0, 1, K);
  cp_commit();

  for (int kt = 0; kt < KT; ++kt) {
    if (kt < KT - 1) { cp_waitg1(); } else { cp_waitg0(); }
    __syncthreads();
    if (kt + 2 < KT) {
      g_prefetch(A, BT, sbase + (uint32_t)((kt + 2) % 3) * STG_B, tid, m0, n0, kt + 2, K);
      cp_commit();
    }

    const uint32_t Ab = sbase + (uint32_t)(kt % 3) * STG_B;
    const uint32_t Bb = Ab + 16384u;
#pragma unroll
    for (int ks = 0; ks < 4; ++ks) {
      uint32_t a[2][4];
      uint32_t b[8][2];
#pragma unroll
      for (int mi = 0; mi < 2; ++mi) {
        int row = wm * 32 + mi * 16 + rA;
        uint32_t ch = (uint32_t)(((ks << 1) | hiA) ^ (row & 7));
        ldsm4(a[mi], Ab + row * 128 + (ch << 4));
      }
#pragma unroll
      for (int j = 0; j < 4; ++j) {
        int row = wn * 64 + j * 16 + rB;
        uint32_t ch = (uint32_t)(((ks << 1) | hiB) ^ (row & 7));
        uint32_t r[4];
        ldsm4(r, Bb + row * 128 + (ch << 4));
        b[2 * j + 0][0] = r[0];
        b[2 * j + 0][1] = r[1];
        b[2 * j + 1][0] = r[2];
        b[2 * j + 1][1] = r[3];
      }
#pragma unroll
      for (int mi = 0; mi < 2; ++mi) {
#pragma unroll
        for (int nj = 0; nj < 8; ++nj) { mma_tf32(acc[mi][nj], a[mi], b[nj]); }
      }
    }
    __syncthreads();
  }

#pragma unroll
  for (int mi = 0; mi < 2; ++mi) {
    int r0 = m0 + wm * 32 + mi * 16 + lg;
#pragma unroll
    for (int nj = 0; nj < 8; ++nj) {
      int col = n0 + wn * 64 + nj * 8 + lt * 2;
#pragma unroll
      for (int half = 0; half < 2; ++half) {
        int row = r0 + half * 8;
        float v0 = acc[mi][nj][half * 2 + 0];
        float v1 = acc[mi][nj][half * 2 + 1];
        if (epi == 1) {
          v0 = rnd_tf32(tanhf(v0));
          v1 = rnd_tf32(tanhf(v1));
        } else if (epi == 2) {
          v0 = rnd_tf32(1.f / (1.f + __expf(-v0)) - 0.5f);
          v1 = rnd_tf32(1.f / (1.f + __expf(-v1)) - 0.5f);
        } else if (epi == 3) {
          v0 += cvec[col]; v1 += cvec[col + 1];
        }
        float2 v2 = make_float2(v0, v1);
        *(float2*)&C[(size_t)row * N + col] = v2;
      }
    }
  }
}

__global__ __launch_bounds__(256, 2)
void gemm_qkv(const float* __restrict__ x,
              const float* __restrict__ WqT, const float* __restrict__ WkT,
              const float* __restrict__ WvT,
              float* __restrict__ qb, float* __restrict__ kb, float* __restrict__ vp) {
  const int xt = blockIdx.x;
  const int m0 = blockIdx.y * 128;
  const float* BT;
  float* C;
  int N, n0, epi;
  if (xt < 8) {
    BT = WqT; C = qb; N = H_N * QKB_N; n0 = xt * 128; epi = 1;
  } else if (xt < 10) {
    BT = WkT; C = kb; N = KV_N * QKB_N; n0 = (xt - 8) * 128; epi = 1;
  } else {
    BT = WvT; C = vp; N = KV_N * VB_N; n0 = (xt - 10) * 128; epi = 2;
  }
  gemm_body(x, BT, C, N, HID_N, m0, n0, epi, (const float*)0);
}

__global__ __launch_bounds__(256, 2)
void gemm_out(const float* __restrict__ obd, const float* __restrict__ WoT,
              float* __restrict__ out, const float* __restrict__ cvec) {
  gemm_body(obd, WoT, out, HID_N, H_N * VB_N, blockIdx.y * 128, blockIdx.x * 128,
            3, cvec);
}

// ---------------------------------------------------------------------------
// Flash attention, tf32 mma.sync. K/V/mask tiles double-buffered via cp.async
// (one __syncthreads per tile; load of kt+1 overlaps compute of kt). V comes
// from g_vpT (pre-transposed) so all tile loads are contiguous cp16.
// Heavy q-tiles dispatched first.
// ---------------------------------------------------------------------------
#define KS_P 68
#define P_P 68
#define KVT_F (64 * KS_P)    // floats per K or V buffer

__device__ __forceinline__ void attn_prefetch(
    uint32_t ksb, uint32_t vsb, uint32_t msb,
    int tid, int b, int kv, int k0) {
#pragma unroll
  for (int it = 0; it < 4; ++it) {
    int c = tid + it * 256;
    int r = c >> 4;          // 0..63 key row
    int ch = c & 15;         // 16B chunk within 64 floats
    cp16(ksb + r * (KS_P * 4) + ch * 16,
         g_kb + (((size_t)b * S_N + k0 + r) * KV_N + kv) * QKB_N + ch * 4);
  }
#pragma unroll
  for (int it = 0; it < 4; ++it) {
    int c = tid + it * 256;
    int vc = c >> 4;         // 0..63 v column
    int ch = c & 15;
    cp16(vsb + vc * (KS_P * 4) + ch * 16,
         g_vpT + ((size_t)b * (KV_N * VB_N) + kv * VB_N + vc) * S_N + k0 + ch * 4);
  }
}

__global__ __launch_bounds__(256)
void attn_mma_kernel(const int* __restrict__ amask,
                     const float* __restrict__ emb0,
                     const float* __restrict__ emb1) {
  extern __shared__ float smn[];
  float* Ks  = smn;                       // [2][64][KS_P]
  float* Vst = Ks + 2 * KVT_F;            // [2][64][KS_P]
  float* Pw  = Vst + 2 * KVT_F;           // [8 warps][16][P_P]
  int*   Ms  = (int*)(Pw + 8 * 16 * P_P); // [2][64]

  const int qt = (int)gridDim.x - 1 - (int)blockIdx.x;  // heavy tiles first
  const int h  = blockIdx.y;
  const int b  = blockIdx.z;
  const int kv = h >> 2;
  const int tid = threadIdx.x;
  const int w = tid >> 5;
  const int lane = tid & 31;
  const int lg = lane >> 2;
  const int lt = lane & 3;
  const int q0 = qt * 128;
  const int r0 = q0 + w * 16 + lg;
  const int r1 = r0 + 8;
  const int rA = lane & 15;
  const int kaddA = ((lane >> 4) << 2);
  const int rB = ((lane >> 4) << 3) + (lane & 7);
  const int kaddB = (((lane >> 3) & 1) << 2);
  const float EXSC = 0.022542110013890053f;  // log2(e)/64

  uint32_t aq[8][4];
  {
    const float* Q0 = g_qb + (((size_t)b * S_N + r0) * H_N + h) * QKB_N;
    const float* Q1 = g_qb + (((size_t)b * S_N + r1) * H_N + h) * QKB_N;
#pragma unroll
    for (int ks = 0; ks < 8; ++ks) {
      aq[ks][0] = __float_as_uint(Q0[ks * 8 + lt]);
      aq[ks][1] = __float_as_uint(Q1[ks * 8 + lt]);
      aq[ks][2] = __float_as_uint(Q0[ks * 8 + lt + 4]);
      aq[ks][3] = __float_as_uint(Q1[ks * 8 + lt + 4]);
    }
  }

  float acc[8][4];
#pragma unroll
  for (int nj = 0; nj < 8; ++nj) {
#pragma unroll
    for (int t = 0; t < 4; ++t) { acc[nj][t] = 0.f; }
  }
  float l0 = 0.f, l1 = 0.f;

  float* Pme = Pw + w * 16 * P_P;
  const uint32_t ks_u = smem_u32(Ks);
  const uint32_t vs_u = smem_u32(Vst);
  const uint32_t ms_u = smem_u32(Ms);

  const int nkt = 2 * qt + 2;

  // prologue: tile 0 -> buffer 0
  attn_prefetch(ks_u, vs_u, ms_u, tid, b, kv, 0);
  if (tid < 16) {
    cp16(ms_u + tid * 16, amask + (size_t)b * S_N + tid * 4);
  }
  cp_commit();

  for (int kt = 0; kt < nkt; ++kt) {
    const int bi = kt & 1;
    cp_waitg0();
    __syncthreads();
    if (kt + 1 < nkt) {
      const int ni = (kt + 1) & 1;
      attn_prefetch(ks_u + ni * (KVT_F * 4), vs_u + ni * (KVT_F * 4),
                    ms_u + ni * 256, tid, b, kv, (kt + 1) * 64);
      if (tid < 16) {
        cp16(ms_u + ni * 256 + tid * 16, amask + (size_t)b * S_N + (kt + 1) * 64 + tid * 4);
      }
      cp_commit();
    }

    const int k0 = kt * 64;
    const float* Ksb = Ks + bi * KVT_F;
    const float* Vsb = Vst + bi * KVT_F;
    const int* Msb = Ms + bi * 64;

    // ---- S = Q @ K^T ----
    float s[8][4];
#pragma unroll
    for (int nj = 0; nj < 8; ++nj) {
#pragma unroll
      for (int t = 0; t < 4; ++t) { s[nj][t] = 0.f; }
    }
#pragma unroll
    for (int ks = 0; ks < 8; ++ks) {
#pragma unroll
      for (int j = 0; j < 4; ++j) {
        uint32_t r[4];
        ldsm4(r, smem_u32(&Ksb[(j * 16 + rB) * KS_P + ks * 8 + kaddB]));
        mma_tf32(s[2 * j + 0], aq[ks], r + 0);
        mma_tf32(s[2 * j + 1], aq[ks], r + 2);
      }
    }

    // ---- probs = exp(s/64), masked -> 0 ----
    float rs0 = 0.f, rs1 = 0.f;
#pragma unroll
    for (int nj = 0; nj < 8; ++nj) {
      int c0i = nj * 8 + lt * 2;
      int kc0 = k0 + c0i;
      int kc1 = kc0 + 1;
      bool mk0 = Msb[c0i] != 0;
      bool mk1 = Msb[c0i + 1] != 0;
      float p00 = (kc0 <= r0 && mk0) ? exp2f(s[nj][0] * EXSC) : 0.f;
      float p01 = (kc1 <= r0 && mk1) ? exp2f(s[nj][1] * EXSC) : 0.f;
      float p10 = (kc0 <= r1 && mk0) ? exp2f(s[nj][2] * EXSC) : 0.f;
      float p11 = (kc1 <= r1 && mk1) ? exp2f(s[nj][3] * EXSC) : 0.f;
      rs0 += p00 + p01;
      rs1 += p10 + p11;
      float2 q2a = make_float2(p00, p01);
      float2 q2b = make_float2(p10, p11);
      *(float2*)&Pme[lg * P_P + nj * 8 + lt * 2] = q2a;
      *(float2*)&Pme[(lg + 8) * P_P + nj * 8 + lt * 2] = q2b;
    }
    rs0 += __shfl_xor_sync(0xffffffffu, rs0, 1);
    rs0 += __shfl_xor_sync(0xffffffffu, rs0, 2);
    rs1 += __shfl_xor_sync(0xffffffffu, rs1, 1);
    rs1 += __shfl_xor_sync(0xffffffffu, rs1, 2);
    l0 += rs0;
    l1 += rs1;
    __syncwarp();

    // ---- O += P @ V' ----
#pragma unroll
    for (int ks = 0; ks < 8; ++ks) {
      uint32_t pr[4];
      ldsm4(pr, smem_u32(&Pme[rA * P_P + ks * 8 + kaddA]));
      uint32_t hi[4];
      hi[0] = f2tf32(__uint_as_float(pr[0]));
      hi[1] = f2tf32(__uint_as_float(pr[1]));
      hi[2] = f2tf32(__uint_as_float(pr[2]));
      hi[3] = f2tf32(__uint_as_float(pr[3]));
#pragma unroll
      for (int j = 0; j < 4; ++j) {
        uint32_t r[4];
        ldsm4(r, smem_u32(&Vsb[(j * 16 + rB) * KS_P + ks * 8 + kaddB]));
        mma_tf32(acc[2 * j + 0], hi, r + 0);
        mma_tf32(acc[2 * j + 1], hi, r + 2);
      }
    }
  }

  // ---- epilogue: centered out-bits (rounded to tf32 for the next GEMM) ----
  float inv0 = 1.f / l0;
  float inv1 = 1.f / l1;
#pragma unroll
  for (int nj = 0; nj < 8; ++nj) {
    int vc = nj * 8 + lt * 2;
    float d0 = emb1[h * VB_N + vc] - emb0[h * VB_N + vc];
    float d1 = emb1[h * VB_N + vc + 1] - emb0[h * VB_N + vc + 1];
    float2 o0 = make_float2(rnd_tf32(acc[nj][0] * inv0 * d0),
                            rnd_tf32(acc[nj][1] * inv0 * d1));
    float2 o1 = make_float2(rnd_tf32(acc[nj][2] * inv1 * d0),
                            rnd_tf32(acc[nj][3] * inv1 * d1));
    *(float2*)&g_obd[(((size_t)b * S_N + r0) * H_N + h) * VB_N + vc] = o0;
    *(float2*)&g_obd[(((size_t)b * S_N + r1) * H_N + h) * VB_N + vc] = o1;
  }
}

// ---------------------------------------------------------------------------
extern "C" void kernel_launch(void* const* d_in, const int* in_sizes, int n_in,
                              void* d_out, int out_size) {
  const float* x  = (const float*)d_in[0];
  const int*   am = (const int*)d_in[1];
  const float* Wq = (const float*)d_in[2];
  const float* Wk = (const float*)d_in[3];
  const float* Wv = (const float*)d_in[4];
  const float* Wo = (const float*)d_in[5];
  const float* e0 = (const float*)d_in[6];
  const float* e1 = (const float*)d_in[7];
  float* out = (float*)d_out;

  float* qb;  float* kb;  float* vp;  float* obd;  float* cvec;
  float* xr;  float* wqt; float* wkt; float* wvt;  float* wot;
  cudaGetSymbolAddress((void**)&qb, g_qb);
  cudaGetSymbolAddress((void**)&kb, g_kb);
  cudaGetSymbolAddress((void**)&vp, g_vp);
  cudaGetSymbolAddress((void**)&obd, g_obd);
  cudaGetSymbolAddress((void**)&cvec, g_cvec);
  cudaGetSymbolAddress((void**)&xr, g_xr);
  cudaGetSymbolAddress((void**)&wqt, g_wqt);
  cudaGetSymbolAddress((void**)&wkt, g_wkt);
  cudaGetSymbolAddress((void**)&wvt, g_wvt);
  cudaGetSymbolAddress((void**)&wot, g_wot);

  const int M = MTOT;

  round_tf32_kernel<<<(M * HID_N / 4 + 255) / 256, 256>>>(x, xr, M * HID_N / 4);
  transpose_round_kernel<<<dim3((H_N * QKB_N) / 32, HID_N / 32), 256>>>(Wq, wqt, HID_N, H_N * QKB_N);
  transpose_round_kernel<<<dim3((KV_N * QKB_N) / 32, HID_N / 32), 256>>>(Wk, wkt, HID_N, KV_N * QKB_N);
  transpose_round_kernel<<<dim3((KV_N * VB_N) / 32, HID_N / 32), 256>>>(Wv, wvt, HID_N, KV_N * VB_N);
  transpose_round_kernel<<<dim3(HID_N / 32, (H_N * VB_N) / 32), 256>>>(Wo, wot, H_N * VB_N, HID_N);
  cvec_kernel<<<HID_N / 64, 256>>>(e0, e1, Wo);

  cudaFuncSetAttribute(gemm_qkv, cudaFuncAttributeMaxDynamicSharedMemorySize, GEMM_DSMEM);
  cudaFuncSetAttribute(gemm_out, cudaFuncAttributeMaxDynamicSharedMemorySize, GEMM_DSMEM);

  gemm_qkv<<<dim3(12, M / 128), 256, GEMM_DSMEM>>>(xr, wqt, wkt, wvt, qb, kb, vp);

  // V transpose for coalesced attention loads
  transpose_v_kernel<<<dim3((KV_N * VB_N) / 32, S_N / 32, B_N), 256>>>();

  size_t asmem = (size_t)(2 * KVT_F + 2 * KVT_F + 8 * 16 * P_P) * sizeof(float)
               + 2 * 64 * sizeof(int);
  cudaFuncSetAttribute(attn_mma_kernel, cudaFuncAttributeMaxDynamicSharedMemorySize, (int)asmem);
  attn_mma_kernel<<<dim3(S_N / 128, H_N, B_N), 256, asmem>>>(am, e0, e1);

  gemm_out<<<dim3(HID_N / 128, M / 128), 256, GEMM_DSMEM>>>(obd, wot, out, cvec);
}

// round 12
// speedup vs baseline: 1.0222x; 1.0222x over previous
#include <cuda_runtime.h>
#include <stdint.h>
#include <math.h>

#define B_N 2
#define S_N 2048
#define HID_N 2048
#define H_N 16
#define KV_N 4
#define QKB_N 64
#define VB_N 64
#define MTOT (B_N * S_N)

// ---- scratch (__device__ globals: allocation-free rule) ----
__device__ float g_qb[(size_t)MTOT * H_N * QKB_N];    // round(tanh(x@Wq))
__device__ float g_kb[(size_t)MTOT * KV_N * QKB_N];   // round(tanh(x@Wk))
__device__ float g_vp[(size_t)MTOT * KV_N * VB_N];    // round(sigm(x@Wv)-0.5)
__device__ float g_vpT[(size_t)B_N * KV_N * VB_N * S_N]; // V transposed [b][kv][vb][s]
__device__ float g_obd[(size_t)MTOT * H_N * VB_N];    // round((ctx-.5)*(e1-e0))
__device__ float g_cvec[HID_N];
__device__ float g_part[(size_t)2 * 12 * MTOT * 128]; // split-K partials [z][xt][m][128]
__device__ float g_wqt[(size_t)(H_N * QKB_N) * HID_N];   // round(Wq^T) [N][K]
__device__ float g_wkt[(size_t)(KV_N * QKB_N) * HID_N];  // round(Wk^T)
__device__ float g_wvt[(size_t)(KV_N * VB_N) * HID_N];   // round(Wv^T)
__device__ float g_wot[(size_t)HID_N * (H_N * VB_N)];    // round(Wo^T)

// ---- helpers ----
__device__ __forceinline__ uint32_t smem_u32(const void* p) {
  return (uint32_t)__cvta_generic_to_shared(p);
}

__device__ __forceinline__ void cp16(uint32_t dst, const void* src) {
  asm volatile("cp.async.cg.shared.global [%0], [%1], 16;"
               : : "r"(dst), "l"(src) : "memory");
}

__device__ __forceinline__ void cp_commit() {
  asm volatile("cp.async.commit_group;" : : : "memory");
}

__device__ __forceinline__ void cp_waitg0() {
  asm volatile("cp.async.wait_group 0;" : : : "memory");
}
__device__ __forceinline__ void cp_waitg1() {
  asm volatile("cp.async.wait_group 1;" : : : "memory");
}

__device__ __forceinline__ uint32_t f2tf32(float v) {
  uint32_t r;
  asm("cvt.rna.tf32.f32 %0, %1;" : "=r"(r) : "f"(v));
  return r;
}

__device__ __forceinline__ float rnd_tf32(float v) {
  return __uint_as_float(f2tf32(v));
}

__device__ __forceinline__ void ldsm4(uint32_t* r, uint32_t a) {
  asm volatile("ldmatrix.sync.aligned.m8n8.x4.shared.b16 {%0,%1,%2,%3}, [%4];"
               : "=r"(r[0]), "=r"(r[1]), "=r"(r[2]), "=r"(r[3])
               : "r"(a));
}

__device__ __forceinline__ void mma_tf32(float* d, const uint32_t* a, const uint32_t* b) {
  asm volatile(
    "mma.sync.aligned.m16n8k8.row.col.f32.tf32.tf32.f32 "
    "{%0,%1,%2,%3}, {%4,%5,%6,%7}, {%8,%9}, {%0,%1,%2,%3};"
    : "+f"(d[0]), "+f"(d[1]), "+f"(d[2]), "+f"(d[3])
    : "r"(a[0]), "r"(a[1]), "r"(a[2]), "r"(a[3]), "r"(b[0]), "r"(b[1]));
}

// ---- merged transpose+round for Wq/Wk/Wv: out[n][k] = rnd(in[k][n]) ----
__global__ void transpose_round_qkv_kernel(const float* __restrict__ Wq,
                                           const float* __restrict__ Wk,
                                           const float* __restrict__ Wv) {
  __shared__ float t[32][33];
  const int tx = threadIdx.x & 31;
  const int ty = threadIdx.x >> 5;
  const int xt = blockIdx.x;       // 0-31 Q, 32-39 K, 40-47 V
  const int k0 = blockIdx.y * 32;
  const float* in;
  float* out;
  int N, n0;
  if (xt < 32) { in = Wq; out = g_wqt; N = 1024; n0 = xt * 32; }
  else if (xt < 40) { in = Wk; out = g_wkt; N = 256; n0 = (xt - 32) * 32; }
  else { in = Wv; out = g_wvt; N = 256; n0 = (xt - 40) * 32; }
#pragma unroll
  for (int i = 0; i < 4; ++i) {
    int k = k0 + ty + i * 8;
    t[ty + i * 8][tx] = in[(size_t)k * N + n0 + tx];
  }
  __syncthreads();
#pragma unroll
  for (int i = 0; i < 4; ++i) {
    int n = n0 + ty + i * 8;
    out[(size_t)n * HID_N + k0 + tx] = rnd_tf32(t[tx][ty + i * 8]);
  }
}

// ---- transpose + round (generic, for Wo): out[n][k] = rnd(in[k][n]) ----
__global__ void transpose_round_kernel(const float* __restrict__ in,
                                       float* __restrict__ out, int K, int N) {
  __shared__ float t[32][33];
  const int tx = threadIdx.x & 31;
  const int ty = threadIdx.x >> 5;
  const int n0 = blockIdx.x * 32;
  const int k0 = blockIdx.y * 32;
#pragma unroll
  for (int i = 0; i < 4; ++i) {
    int k = k0 + ty + i * 8;
    t[ty + i * 8][tx] = in[(size_t)k * N + n0 + tx];
  }
  __syncthreads();
#pragma unroll
  for (int i = 0; i < 4; ++i) {
    int n = n0 + ty + i * 8;
    out[(size_t)n * K + k0 + tx] = rnd_tf32(t[tx][ty + i * 8]);
  }
}

// ---- V transpose: g_vp[b][s][n] -> g_vpT[b][n][s] ----
__global__ void transpose_v_kernel() {
  __shared__ float t[32][33];
  const int tx = threadIdx.x & 31;
  const int ty = threadIdx.x >> 5;
  const int n0 = blockIdx.x * 32;
  const int s0 = blockIdx.y * 32;
  const int b  = blockIdx.z;
#pragma unroll
  for (int i = 0; i < 4; ++i) {
    t[ty + i * 8][tx] = g_vp[((size_t)b * S_N + s0 + ty + i * 8) * (KV_N * VB_N) + n0 + tx];
  }
  __syncthreads();
#pragma unroll
  for (int i = 0; i < 4; ++i) {
    g_vpT[((size_t)b * (KV_N * VB_N) + n0 + ty + i * 8) * S_N + s0 + tx] = t[tx][ty + i * 8];
  }
}

// ---- cvec[n] = sum_k 0.5*(e0[k]+e1[k]) * Wo[k][n]; k-split x4 + reduce ----
__global__ void cvec_kernel(const float* __restrict__ e0, const float* __restrict__ e1,
                            const float* __restrict__ Wo) {
  __shared__ float part[4][64];
  const int tid = threadIdx.x;
  const int col = tid & 63;
  const int sl = tid >> 6;
  const int n = blockIdx.x * 64 + col;
  float s = 0.f;
  const int k0 = sl * 256;
  for (int k = k0; k < k0 + 256; ++k) {
    s = fmaf(0.5f * (e0[k] + e1[k]), Wo[(size_t)k * HID_N + n], s);
  }
  part[sl][col] = s;
  __syncthreads();
  if (sl == 0) {
    g_cvec[n] = part[0][col] + part[1][col] + part[2][col] + part[3][col];
  }
}

// ---------------------------------------------------------------------------
// TF32 GEMM body: C[.., Nc] tile = epi(A[M,ld sliced K] @ BT[N,ld]^T).
// 128x128x32 tile, 3-stage cp.async ring, XOR-chunk swizzle, mma + ldmatrix.
// cvtA: round A fragments at use (for unrounded fp32 A).
// n0b: B-row offset; C written at columns [n0c, n0c+128) with row stride Nc.
// ---------------------------------------------------------------------------
#define STG_B 32768u
#define GEMM_DSMEM (3 * 32768)

__device__ __forceinline__ void g_prefetch(
    const float* __restrict__ A, const float* __restrict__ BT,
    uint32_t sA, int tid, int m0, int n0b, int kt, int ld) {
#pragma unroll
  for (int it = 0; it < 4; ++it) {
    int c = tid + it * 256;
    int r = c >> 3;
    int ch = c & 7;
    cp16(sA + r * 128 + ((uint32_t)(ch ^ (r & 7)) << 4),
         A + (size_t)(m0 + r) * ld + kt * 32 + ch * 4);
  }
#pragma unroll
  for (int it = 0; it < 4; ++it) {
    int c = tid + it * 256;
    int r = c >> 3;
    int ch = c & 7;
    cp16(sA + 16384u + r * 128 + ((uint32_t)(ch ^ (r & 7)) << 4),
         BT + (size_t)(n0b + r) * ld + kt * 32 + ch * 4);
  }
}

__device__ __forceinline__ void gemm_body(
    const float* __restrict__ A, const float* __restrict__ BT,
    float* __restrict__ C, int Nc, int K, int ld, int m0, int n0b, int n0c,
    int epi, int cvtA, const float* __restrict__ cvec) {
  extern __shared__ float gsm[];
  const int tid = threadIdx.x;
  const int wid = tid >> 5;
  const int lane = tid & 31;
  const int wm = wid & 3;
  const int wn = wid >> 2;
  const int lg = lane >> 2;
  const int lt = lane & 3;
  const int rA = lane & 15;
  const int hiA = lane >> 4;
  const int rB = ((lane >> 4) << 3) + (lane & 7);
  const int hiB = (lane >> 3) & 1;
  const uint32_t sbase = smem_u32(gsm);

  float acc[2][8][4];
#pragma unroll
  for (int i = 0; i < 2; ++i) {
#pragma unroll
    for (int j = 0; j < 8; ++j) {
#pragma unroll
      for (int t = 0; t < 4; ++t) { acc[i][j][t] = 0.f; }
    }
  }

  const int KT = K / 32;
  g_prefetch(A, BT, sbase + 0 * STG_B, tid, m0, n0b, 0, ld);
  cp_commit();
  g_prefetch(A, BT, sbase + 1 * STG_B, tid, m0, n0b, 1, ld);
  cp_commit();

  for (int kt = 0; kt < KT; ++kt) {
    if (kt < KT - 1) { cp_waitg1(); } else { cp_waitg0(); }
    __syncthreads();
    if (kt + 2 < KT) {
      g_prefetch(A, BT, sbase + (uint32_t)((kt + 2) % 3) * STG_B, tid, m0, n0b, kt + 2, ld);
      cp_commit();
    }

    const uint32_t Ab = sbase + (uint32_t)(kt % 3) * STG_B;
    const uint32_t Bb = Ab + 16384u;
#pragma unroll
    for (int ks = 0; ks < 4; ++ks) {
      uint32_t a[2][4];
      uint32_t b[8][2];
#pragma unroll
      for (int mi = 0; mi < 2; ++mi) {
        int row = wm * 32 + mi * 16 + rA;
        uint32_t ch = (uint32_t)(((ks << 1) | hiA) ^ (row & 7));
        ldsm4(a[mi], Ab + row * 128 + (ch << 4));
        if (cvtA) {
#pragma unroll
          for (int t = 0; t < 4; ++t) {
            a[mi][t] = f2tf32(__uint_as_float(a[mi][t]));
          }
        }
      }
#pragma unroll
      for (int j = 0; j < 4; ++j) {
        int row = wn * 64 + j * 16 + rB;
        uint32_t ch = (uint32_t)(((ks << 1) | hiB) ^ (row & 7));
        uint32_t r[4];
        ldsm4(r, Bb + row * 128 + (ch << 4));
        b[2 * j + 0][0] = r[0];
        b[2 * j + 0][1] = r[1];
        b[2 * j + 1][0] = r[2];
        b[2 * j + 1][1] = r[3];
      }
#pragma unroll
      for (int mi = 0; mi < 2; ++mi) {
#pragma unroll
        for (int nj = 0; nj < 8; ++nj) { mma_tf32(acc[mi][nj], a[mi], b[nj]); }
      }
    }
    __syncthreads();
  }

#pragma unroll
  for (int mi = 0; mi < 2; ++mi) {
    int r0 = m0 + wm * 32 + mi * 16 + lg;
#pragma unroll
    for (int nj = 0; nj < 8; ++nj) {
      int col = n0c + wn * 64 + nj * 8 + lt * 2;
#pragma unroll
      for (int half = 0; half < 2; ++half) {
        int row = r0 + half * 8;
        float v0 = acc[mi][nj][half * 2 + 0];
        float v1 = acc[mi][nj][half * 2 + 1];
        if (epi == 3) {
          v0 += cvec[col]; v1 += cvec[col + 1];
        }
        float2 v2 = make_float2(v0, v1);
        *(float2*)&C[(size_t)row * Nc + col] = v2;
      }
    }
  }
}

// Split-K Q/K/V projection: grid (12, 32, 2). z = K half. Raw partials.
__global__ __launch_bounds__(256, 2)
void gemm_qkv_sk(const float* __restrict__ x,
                 const float* __restrict__ WqT, const float* __restrict__ WkT,
                 const float* __restrict__ WvT) {
  const int xt = blockIdx.x;
  const int m0 = blockIdx.y * 128;
  const int z = blockIdx.z;
  const float* BT;
  int n0b;
  if (xt < 8) { BT = WqT; n0b = xt * 128; }
  else if (xt < 10) { BT = WkT; n0b = (xt - 8) * 128; }
  else { BT = WvT; n0b = (xt - 10) * 128; }
  float* C = g_part + (size_t)(z * 12 + xt) * MTOT * 128;
  gemm_body(x + (size_t)z * 1024, BT + (size_t)z * 1024, C,
            128, 1024, HID_N, m0, n0b, 0, 0, 1, (const float*)0);
}

// Combine split-K halves + epilogues -> qb/kb/vp
__global__ void qkv_combine_kernel() {
  const int xt = blockIdx.y;
  const int idx4 = blockIdx.x * 256 + threadIdx.x;   // 0..131071 (f4 within xt)
  const size_t off = (size_t)xt * MTOT * 128 + (size_t)idx4 * 4;
  float4 a = *(const float4*)(g_part + off);
  float4 b = *(const float4*)(g_part + (size_t)12 * MTOT * 128 + off);
  a.x += b.x; a.y += b.y; a.z += b.z; a.w += b.w;
  if (xt < 10) {
    a.x = rnd_tf32(tanhf(a.x));
    a.y = rnd_tf32(tanhf(a.y));
    a.z = rnd_tf32(tanhf(a.z));
    a.w = rnd_tf32(tanhf(a.w));
  } else {
    a.x = rnd_tf32(1.f / (1.f + __expf(-a.x)) - 0.5f);
    a.y = rnd_tf32(1.f / (1.f + __expf(-a.y)) - 0.5f);
    a.z = rnd_tf32(1.f / (1.f + __expf(-a.z)) - 0.5f);
    a.w = rnd_tf32(1.f / (1.f + __expf(-a.w)) - 0.5f);
  }
  const int row = idx4 >> 5;           // 32 f4 per 128-col row
  const int col = (idx4 & 31) * 4;
  if (xt < 8) {
    *(float4*)&g_qb[(size_t)row * (H_N * QKB_N) + xt * 128 + col] = a;
  } else if (xt < 10) {
    *(float4*)&g_kb[(size_t)row * (KV_N * QKB_N) + (xt - 8) * 128 + col] = a;
  } else {
    *(float4*)&g_vp[(size_t)row * (KV_N * VB_N) + (xt - 10) * 128 + col] = a;
  }
}

// Output projection: out = obd @ Wo + cvec
__global__ __launch_bounds__(256, 2)
void gemm_out(const float* __restrict__ obd, const float* __restrict__ WoT,
              float* __restrict__ out, const float* __restrict__ cvec) {
  const int n0 = blockIdx.x * 128;
  gemm_body(obd, WoT, out, HID_N, H_N * VB_N, H_N * VB_N,
            blockIdx.y * 128, n0, n0, 3, 0, cvec);
}

// ---------------------------------------------------------------------------
// Flash attention, tf32 mma.sync. Double-buffered cp.async K/V/mask tiles,
// per-warp causal skip of fully-masked tiles, heavy q-tiles first.
// ---------------------------------------------------------------------------
#define KS_P 68
#define P_P 68
#define KVT_F (64 * KS_P)

__device__ __forceinline__ void attn_prefetch(
    uint32_t ksb, uint32_t vsb, int tid, int b, int kv, int k0) {
#pragma unroll
  for (int it = 0; it < 4; ++it) {
    int c = tid + it * 256;
    int r = c >> 4;
    int ch = c & 15;
    cp16(ksb + r * (KS_P * 4) + ch * 16,
         g_kb + (((size_t)b * S_N + k0 + r) * KV_N + kv) * QKB_N + ch * 4);
  }
#pragma unroll
  for (int it = 0; it < 4; ++it) {
    int c = tid + it * 256;
    int vc = c >> 4;
    int ch = c & 15;
    cp16(vsb + vc * (KS_P * 4) + ch * 16,
         g_vpT + ((size_t)b * (KV_N * VB_N) + kv * VB_N + vc) * S_N + k0 + ch * 4);
  }
}

__global__ __launch_bounds__(256)
void attn_mma_kernel(const int* __restrict__ amask,
                     const float* __restrict__ emb0,
                     const float* __restrict__ emb1) {
  extern __shared__ float smn[];
  float* Ks  = smn;                       // [2][64][KS_P]
  float* Vst = Ks + 2 * KVT_F;            // [2][64][KS_P]
  float* Pw  = Vst + 2 * KVT_F;           // [8 warps][16][P_P]
  int*   Ms  = (int*)(Pw + 8 * 16 * P_P); // [2][64]

  const int qt = (int)gridDim.x - 1 - (int)blockIdx.x;  // heavy tiles first
  const int h  = blockIdx.y;
  const int b  = blockIdx.z;
  const int kv = h >> 2;
  const int tid = threadIdx.x;
  const int w = tid >> 5;
  const int lane = tid & 31;
  const int lg = lane >> 2;
  const int lt = lane & 3;
  const int q0 = qt * 128;
  const int r0 = q0 + w * 16 + lg;
  const int r1 = r0 + 8;
  const int qmax_w = q0 + w * 16 + 15;    // warp's max q row
  const int rA = lane & 15;
  const int kaddA = ((lane >> 4) << 2);
  const int rB = ((lane >> 4) << 3) + (lane & 7);
  const int kaddB = (((lane >> 3) & 1) << 2);
  const float EXSC = 0.022542110013890053f;  // log2(e)/64

  uint32_t aq[8][4];
  {
    const float* Q0 = g_qb + (((size_t)b * S_N + r0) * H_N + h) * QKB_N;
    const float* Q1 = g_qb + (((size_t)b * S_N + r1) * H_N + h) * QKB_N;
#pragma unroll
    for (int ks = 0; ks < 8; ++ks) {
      aq[ks][0] = __float_as_uint(Q0[ks * 8 + lt]);
      aq[ks][1] = __float_as_uint(Q1[ks * 8 + lt]);
      aq[ks][2] = __float_as_uint(Q0[ks * 8 + lt + 4]);
      aq[ks][3] = __float_as_uint(Q1[ks * 8 + lt + 4]);
    }
  }

  float acc[8][4];
#pragma unroll
  for (int nj = 0; nj < 8; ++nj) {
#pragma unroll
    for (int t = 0; t < 4; ++t) { acc[nj][t] = 0.f; }
  }
  float l0 = 0.f, l1 = 0.f;

  float* Pme = Pw + w * 16 * P_P;
  const uint32_t ks_u = smem_u32(Ks);
  const uint32_t vs_u = smem_u32(Vst);
  const uint32_t ms_u = smem_u32(Ms);

  const int nkt = 2 * qt + 2;

  attn_prefetch(ks_u, vs_u, tid, b, kv, 0);
  if (tid < 16) {
    cp16(ms_u + tid * 16, amask + (size_t)b * S_N + tid * 4);
  }
  cp_commit();

  for (int kt = 0; kt < nkt; ++kt) {
    const int bi = kt & 1;
    cp_waitg0();
    __syncthreads();
    if (kt + 1 < nkt) {
      const int ni = (kt + 1) & 1;
      attn_prefetch(ks_u + ni * (KVT_F * 4), vs_u + ni * (KVT_F * 4),
                    tid, b, kv, (kt + 1) * 64);
      if (tid < 16) {
        cp16(ms_u + ni * 256 + tid * 16, amask + (size_t)b * S_N + (kt + 1) * 64 + tid * 4);
      }
      cp_commit();
    }

    const int k0 = kt * 64;
    if (k0 > qmax_w) { continue; }      // fully causally masked for this warp

    const float* Ksb = Ks + bi * KVT_F;
    const float* Vsb = Vst + bi * KVT_F;
    const int* Msb = Ms + bi * 64;

    // ---- S = Q @ K^T ----
    float s[8][4];
#pragma unroll
    for (int nj = 0; nj < 8; ++nj) {
#pragma unroll
      for (int t = 0; t < 4; ++t) { s[nj][t] = 0.f; }
    }
#pragma unroll
    for (int ks = 0; ks < 8; ++ks) {
#pragma unroll
      for (int j = 0; j < 4; ++j) {
        uint32_t r[4];
        ldsm4(r, smem_u32(&Ksb[(j * 16 + rB) * KS_P + ks * 8 + kaddB]));
        mma_tf32(s[2 * j + 0], aq[ks], r + 0);
        mma_tf32(s[2 * j + 1], aq[ks], r + 2);
      }
    }

    // ---- probs = exp(s/64), masked -> 0 ----
    float rs0 = 0.f, rs1 = 0.f;
#pragma unroll
    for (int nj = 0; nj < 8; ++nj) {
      int c0i = nj * 8 + lt * 2;
      int kc0 = k0 + c0i;
      int kc1 = kc0 + 1;
      bool mk0 = Msb[c0i] != 0;
      bool mk1 = Msb[c0i + 1] != 0;
      float p00 = (kc0 <= r0 && mk0) ? exp2f(s[nj][0] * EXSC) : 0.f;
      float p01 = (kc1 <= r0 && mk1) ? exp2f(s[nj][1] * EXSC) : 0.f;
      float p10 = (kc0 <= r1 && mk0) ? exp2f(s[nj][2] * EXSC) : 0.f;
      float p11 = (kc1 <= r1 && mk1) ? exp2f(s[nj][3] * EXSC) : 0.f;
      rs0 += p00 + p01;
      rs1 += p10 + p11;
      float2 q2a = make_float2(p00, p01);
      float2 q2b = make_float2(p10, p11);
      *(float2*)&Pme[lg * P_P + nj * 8 + lt * 2] = q2a;
      *(float2*)&Pme[(lg + 8) * P_P + nj * 8 + lt * 2] = q2b;
    }
    rs0 += __shfl_xor_sync(0xffffffffu, rs0, 1);
    rs0 += __shfl_xor_sync(0xffffffffu, rs0, 2);
    rs1 += __shfl_xor_sync(0xffffffffu, rs1, 1);
    rs1 += __shfl_xor_sync(0xffffffffu, rs1, 2);
    l0 += rs0;
    l1 += rs1;
    __syncwarp();

    // ---- O += P @ V' ----
#pragma unroll
    for (int ks = 0; ks < 8; ++ks) {
      uint32_t pr[4];
      ldsm4(pr, smem_u32(&Pme[rA * P_P + ks * 8 + kaddA]));
      uint32_t hi[4];
      hi[0] = f2tf32(__uint_as_float(pr[0]));
      hi[1] = f2tf32(__uint_as_float(pr[1]));
      hi[2] = f2tf32(__uint_as_float(pr[2]));
      hi[3] = f2tf32(__uint_as_float(pr[3]));
#pragma unroll
      for (int j = 0; j < 4; ++j) {
        uint32_t r[4];
        ldsm4(r, smem_u32(&Vsb[(j * 16 + rB) * KS_P + ks * 8 + kaddB]));
        mma_tf32(acc[2 * j + 0], hi, r + 0);
        mma_tf32(acc[2 * j + 1], hi, r + 2);
      }
    }
  }

  // ---- epilogue: centered out-bits (rounded to tf32 for the next GEMM) ----
  float inv0 = 1.f / l0;
  float inv1 = 1.f / l1;
#pragma unroll
  for (int nj = 0; nj < 8; ++nj) {
    int vc = nj * 8 + lt * 2;
    float d0 = emb1[h * VB_N + vc] - emb0[h * VB_N + vc];
    float d1 = emb1[h * VB_N + vc + 1] - emb0[h * VB_N + vc + 1];
    float2 o0 = make_float2(rnd_tf32(acc[nj][0] * inv0 * d0),
                            rnd_tf32(acc[nj][1] * inv0 * d1));
    float2 o1 = make_float2(rnd_tf32(acc[nj][2] * inv1 * d0),
                            rnd_tf32(acc[nj][3] * inv1 * d1));
    *(float2*)&g_obd[(((size_t)b * S_N + r0) * H_N + h) * VB_N + vc] = o0;
    *(float2*)&g_obd[(((size_t)b * S_N + r1) * H_N + h) * VB_N + vc] = o1;
  }
}

// ---------------------------------------------------------------------------
extern "C" void kernel_launch(void* const* d_in, const int* in_sizes, int n_in,
                              void* d_out, int out_size) {
  const float* x  = (const float*)d_in[0];
  const int*   am = (const int*)d_in[1];
  const float* Wq = (const float*)d_in[2];
  const float* Wk = (const float*)d_in[3];
  const float* Wv = (const float*)d_in[4];
  const float* Wo = (const float*)d_in[5];
  const float* e0 = (const float*)d_in[6];
  const float* e1 = (const float*)d_in[7];
  float* out = (float*)d_out;

  float* obd;  float* cvec;
  float* wqt; float* wkt; float* wvt;  float* wot;
  cudaGetSymbolAddress((void**)&obd, g_obd);
  cudaGetSymbolAddress((void**)&cvec, g_cvec);
  cudaGetSymbolAddress((void**)&wqt, g_wqt);
  cudaGetSymbolAddress((void**)&wkt, g_wkt);
  cudaGetSymbolAddress((void**)&wvt, g_wvt);
  cudaGetSymbolAddress((void**)&wot, g_wot);

  const int M = MTOT;

  // weight transposes (+tf32 round) and cvec
  transpose_round_qkv_kernel<<<dim3(48, HID_N / 32), 256>>>(Wq, Wk, Wv);
  transpose_round_kernel<<<dim3(HID_N / 32, (H_N * VB_N) / 32), 256>>>(Wo, wot, H_N * VB_N, HID_N);
  cvec_kernel<<<HID_N / 64, 256>>>(e0, e1, Wo);

  cudaFuncSetAttribute(gemm_qkv_sk, cudaFuncAttributeMaxDynamicSharedMemorySize, GEMM_DSMEM);
  cudaFuncSetAttribute(gemm_out, cudaFuncAttributeMaxDynamicSharedMemorySize, GEMM_DSMEM);

  // split-K Q/K/V projections + combine (epilogues in combine)
  gemm_qkv_sk<<<dim3(12, M / 128, 2), 256, GEMM_DSMEM>>>(x, wqt, wkt, wvt);
  qkv_combine_kernel<<<dim3(M * 128 / (256 * 4), 12), 256>>>();

  // V transpose for coalesced attention loads
  transpose_v_kernel<<<dim3((KV_N * VB_N) / 32, S_N / 32, B_N), 256>>>();

  size_t asmem = (size_t)(2 * KVT_F + 2 * KVT_F + 8 * 16 * P_P) * sizeof(float)
               + 2 * 64 * sizeof(int);
  cudaFuncSetAttribute(attn_mma_kernel, cudaFuncAttributeMaxDynamicSharedMemorySize, (int)asmem);
  attn_mma_kernel<<<dim3(S_N / 128, H_N, B_N), 256, asmem>>>(am, e0, e1);

  gemm_out<<<dim3(HID_N / 128, M / 128), 256, GEMM_DSMEM>>>(obd, wot, out, cvec);
}

// round 13
// speedup vs baseline: 1.0968x; 1.0729x over previous
#include <cuda_runtime.h>
#include <stdint.h>
#include <math.h>

#define B_N 2
#define S_N 2048
#define HID_N 2048
#define H_N 16
#define KV_N 4
#define QKB_N 64
#define VB_N 64
#define MTOT (B_N * S_N)

// ---- scratch (__device__ globals: allocation-free rule) ----
__device__ float g_qb[(size_t)MTOT * H_N * QKB_N];    // round(tanh(x@Wq))
__device__ float g_kb[(size_t)MTOT * KV_N * QKB_N];   // round(tanh(x@Wk))
__device__ float g_vp[(size_t)MTOT * KV_N * VB_N];    // round(sigm(x@Wv)-0.5)
__device__ float g_vpT[(size_t)B_N * KV_N * VB_N * S_N]; // V transposed [b][kv][vb][s]
__device__ float g_obd[(size_t)MTOT * H_N * VB_N];    // round((ctx-.5)*(e1-e0))
__device__ float g_cvec[HID_N];
__device__ float g_part[(size_t)2 * 12 * MTOT * 128]; // split-K partials [z][xt][m][128]
__device__ float g_wqt[(size_t)(H_N * QKB_N) * HID_N];   // round(Wq^T) [N][K]
__device__ float g_wkt[(size_t)(KV_N * QKB_N) * HID_N];  // round(Wk^T)
__device__ float g_wvt[(size_t)(KV_N * VB_N) * HID_N];   // round(Wv^T)
__device__ float g_wot[(size_t)HID_N * (H_N * VB_N)];    // round(Wo^T)

// ---- helpers ----
__device__ __forceinline__ uint32_t smem_u32(const void* p) {
  return (uint32_t)__cvta_generic_to_shared(p);
}

__device__ __forceinline__ void cp16(uint32_t dst, const void* src) {
  asm volatile("cp.async.cg.shared.global [%0], [%1], 16;"
               : : "r"(dst), "l"(src) : "memory");
}

__device__ __forceinline__ void cp_commit() {
  asm volatile("cp.async.commit_group;" : : : "memory");
}

__device__ __forceinline__ void cp_waitg0() {
  asm volatile("cp.async.wait_group 0;" : : : "memory");
}
__device__ __forceinline__ void cp_waitg1() {
  asm volatile("cp.async.wait_group 1;" : : : "memory");
}

__device__ __forceinline__ uint32_t f2tf32(float v) {
  uint32_t r;
  asm("cvt.rna.tf32.f32 %0, %1;" : "=r"(r) : "f"(v));
  return r;
}

__device__ __forceinline__ float rnd_tf32(float v) {
  return __uint_as_float(f2tf32(v));
}

__device__ __forceinline__ void ldsm4(uint32_t* r, uint32_t a) {
  asm volatile("ldmatrix.sync.aligned.m8n8.x4.shared.b16 {%0,%1,%2,%3}, [%4];"
               : "=r"(r[0]), "=r"(r[1]), "=r"(r[2]), "=r"(r[3])
               : "r"(a));
}

__device__ __forceinline__ void mma_tf32(float* d, const uint32_t* a, const uint32_t* b) {
  asm volatile(
    "mma.sync.aligned.m16n8k8.row.col.f32.tf32.tf32.f32 "
    "{%0,%1,%2,%3}, {%4,%5,%6,%7}, {%8,%9}, {%0,%1,%2,%3};"
    : "+f"(d[0]), "+f"(d[1]), "+f"(d[2]), "+f"(d[3])
    : "r"(a[0]), "r"(a[1]), "r"(a[2]), "r"(a[3]), "r"(b[0]), "r"(b[1]));
}

// ---- merged transpose+round for Wq/Wk/Wv: out[n][k] = rnd(in[k][n]) ----
__global__ void transpose_round_qkv_kernel(const float* __restrict__ Wq,
                                           const float* __restrict__ Wk,
                                           const float* __restrict__ Wv) {
  __shared__ float t[32][33];
  const int tx = threadIdx.x & 31;
  const int ty = threadIdx.x >> 5;
  const int xt = blockIdx.x;       // 0-31 Q, 32-39 K, 40-47 V
  const int k0 = blockIdx.y * 32;
  const float* in;
  float* out;
  int N, n0;
  if (xt < 32) { in = Wq; out = g_wqt; N = 1024; n0 = xt * 32; }
  else if (xt < 40) { in = Wk; out = g_wkt; N = 256; n0 = (xt - 32) * 32; }
  else { in = Wv; out = g_wvt; N = 256; n0 = (xt - 40) * 32; }
#pragma unroll
  for (int i = 0; i < 4; ++i) {
    int k = k0 + ty + i * 8;
    t[ty + i * 8][tx] = in[(size_t)k * N + n0 + tx];
  }
  __syncthreads();
#pragma unroll
  for (int i = 0; i < 4; ++i) {
    int n = n0 + ty + i * 8;
    out[(size_t)n * HID_N + k0 + tx] = rnd_tf32(t[tx][ty + i * 8]);
  }
}

// ---- transpose + round (generic, for Wo): out[n][k] = rnd(in[k][n]) ----
__global__ void transpose_round_kernel(const float* __restrict__ in,
                                       float* __restrict__ out, int K, int N) {
  __shared__ float t[32][33];
  const int tx = threadIdx.x & 31;
  const int ty = threadIdx.x >> 5;
  const int n0 = blockIdx.x * 32;
  const int k0 = blockIdx.y * 32;
#pragma unroll
  for (int i = 0; i < 4; ++i) {
    int k = k0 + ty + i * 8;
    t[ty + i * 8][tx] = in[(size_t)k * N + n0 + tx];
  }
  __syncthreads();
#pragma unroll
  for (int i = 0; i < 4; ++i) {
    int n = n0 + ty + i * 8;
    out[(size_t)n * K + k0 + tx] = rnd_tf32(t[tx][ty + i * 8]);
  }
}

// ---- V transpose: g_vp[b][s][n] -> g_vpT[b][n][s] ----
__global__ void transpose_v_kernel() {
  __shared__ float t[32][33];
  const int tx = threadIdx.x & 31;
  const int ty = threadIdx.x >> 5;
  const int n0 = blockIdx.x * 32;
  const int s0 = blockIdx.y * 32;
  const int b  = blockIdx.z;
#pragma unroll
  for (int i = 0; i < 4; ++i) {
    t[ty + i * 8][tx] = g_vp[((size_t)b * S_N + s0 + ty + i * 8) * (KV_N * VB_N) + n0 + tx];
  }
  __syncthreads();
#pragma unroll
  for (int i = 0; i < 4; ++i) {
    g_vpT[((size_t)b * (KV_N * VB_N) + n0 + ty + i * 8) * S_N + s0 + tx] = t[tx][ty + i * 8];
  }
}

// ---- cvec[n] = sum_k 0.5*(e0[k]+e1[k]) * Wo[k][n]; k-split x4 + reduce ----
__global__ void cvec_kernel(const float* __restrict__ e0, const float* __restrict__ e1,
                            const float* __restrict__ Wo) {
  __shared__ float part[4][64];
  const int tid = threadIdx.x;
  const int col = tid & 63;
  const int sl = tid >> 6;
  const int n = blockIdx.x * 64 + col;
  float s = 0.f;
  const int k0 = sl * 256;
  for (int k = k0; k < k0 + 256; ++k) {
    s = fmaf(0.5f * (e0[k] + e1[k]), Wo[(size_t)k * HID_N + n], s);
  }
  part[sl][col] = s;
  __syncthreads();
  if (sl == 0) {
    g_cvec[n] = part[0][col] + part[1][col] + part[2][col] + part[3][col];
  }
}

// ---------------------------------------------------------------------------
// TF32 GEMM body: C[.., Nc] tile = epi(A[M,ld sliced K] @ BT[N,ld]^T).
// 128x128x32 tile, 3-stage cp.async ring, XOR-chunk swizzle, mma + ldmatrix.
// ---------------------------------------------------------------------------
#define STG_B 32768u
#define GEMM_DSMEM (3 * 32768)

__device__ __forceinline__ void g_prefetch(
    const float* __restrict__ A, const float* __restrict__ BT,
    uint32_t sA, int tid, int m0, int n0b, int kt, int ld) {
#pragma unroll
  for (int it = 0; it < 4; ++it) {
    int c = tid + it * 256;
    int r = c >> 3;
    int ch = c & 7;
    cp16(sA + r * 128 + ((uint32_t)(ch ^ (r & 7)) << 4),
         A + (size_t)(m0 + r) * ld + kt * 32 + ch * 4);
  }
#pragma unroll
  for (int it = 0; it < 4; ++it) {
    int c = tid + it * 256;
    int r = c >> 3;
    int ch = c & 7;
    cp16(sA + 16384u + r * 128 + ((uint32_t)(ch ^ (r & 7)) << 4),
         BT + (size_t)(n0b + r) * ld + kt * 32 + ch * 4);
  }
}

__device__ __forceinline__ void gemm_body(
    const float* __restrict__ A, const float* __restrict__ BT,
    float* __restrict__ C, int Nc, int K, int ld, int m0, int n0b, int n0c,
    int epi, int cvtA, const float* __restrict__ cvec) {
  extern __shared__ float gsm[];
  const int tid = threadIdx.x;
  const int wid = tid >> 5;
  const int lane = tid & 31;
  const int wm = wid & 3;
  const int wn = wid >> 2;
  const int lg = lane >> 2;
  const int lt = lane & 3;
  const int rA = lane & 15;
  const int hiA = lane >> 4;
  const int rB = ((lane >> 4) << 3) + (lane & 7);
  const int hiB = (lane >> 3) & 1;
  const uint32_t sbase = smem_u32(gsm);

  float acc[2][8][4];
#pragma unroll
  for (int i = 0; i < 2; ++i) {
#pragma unroll
    for (int j = 0; j < 8; ++j) {
#pragma unroll
      for (int t = 0; t < 4; ++t) { acc[i][j][t] = 0.f; }
    }
  }

  const int KT = K / 32;
  g_prefetch(A, BT, sbase + 0 * STG_B, tid, m0, n0b, 0, ld);
  cp_commit();
  g_prefetch(A, BT, sbase + 1 * STG_B, tid, m0, n0b, 1, ld);
  cp_commit();

  for (int kt = 0; kt < KT; ++kt) {
    if (kt < KT - 1) { cp_waitg1(); } else { cp_waitg0(); }
    __syncthreads();
    if (kt + 2 < KT) {
      g_prefetch(A, BT, sbase + (uint32_t)((kt + 2) % 3) * STG_B, tid, m0, n0b, kt + 2, ld);
      cp_commit();
    }

    const uint32_t Ab = sbase + (uint32_t)(kt % 3) * STG_B;
    const uint32_t Bb = Ab + 16384u;
#pragma unroll
    for (int ks = 0; ks < 4; ++ks) {
      uint32_t a[2][4];
      uint32_t b[8][2];
#pragma unroll
      for (int mi = 0; mi < 2; ++mi) {
        int row = wm * 32 + mi * 16 + rA;
        uint32_t ch = (uint32_t)(((ks << 1) | hiA) ^ (row & 7));
        ldsm4(a[mi], Ab + row * 128 + (ch << 4));
        if (cvtA) {
#pragma unroll
          for (int t = 0; t < 4; ++t) {
            a[mi][t] = f2tf32(__uint_as_float(a[mi][t]));
          }
        }
      }
#pragma unroll
      for (int j = 0; j < 4; ++j) {
        int row = wn * 64 + j * 16 + rB;
        uint32_t ch = (uint32_t)(((ks << 1) | hiB) ^ (row & 7));
        uint32_t r[4];
        ldsm4(r, Bb + row * 128 + (ch << 4));
        b[2 * j + 0][0] = r[0];
        b[2 * j + 0][1] = r[1];
        b[2 * j + 1][0] = r[2];
        b[2 * j + 1][1] = r[3];
      }
#pragma unroll
      for (int mi = 0; mi < 2; ++mi) {
#pragma unroll
        for (int nj = 0; nj < 8; ++nj) { mma_tf32(acc[mi][nj], a[mi], b[nj]); }
      }
    }
    __syncthreads();
  }

#pragma unroll
  for (int mi = 0; mi < 2; ++mi) {
    int r0 = m0 + wm * 32 + mi * 16 + lg;
#pragma unroll
    for (int nj = 0; nj < 8; ++nj) {
      int col = n0c + wn * 64 + nj * 8 + lt * 2;
#pragma unroll
      for (int half = 0; half < 2; ++half) {
        int row = r0 + half * 8;
        float v0 = acc[mi][nj][half * 2 + 0];
        float v1 = acc[mi][nj][half * 2 + 1];
        if (epi == 3) {
          v0 += cvec[col]; v1 += cvec[col + 1];
        }
        float2 v2 = make_float2(v0, v1);
        *(float2*)&C[(size_t)row * Nc + col] = v2;
      }
    }
  }
}

// Split-K Q/K/V projection: grid (12, 32, 2). z = K half. Raw partials.
__global__ __launch_bounds__(256, 2)
void gemm_qkv_sk(const float* __restrict__ x,
                 const float* __restrict__ WqT, const float* __restrict__ WkT,
                 const float* __restrict__ WvT) {
  const int xt = blockIdx.x;
  const int m0 = blockIdx.y * 128;
  const int z = blockIdx.z;
  const float* BT;
  int n0b;
  if (xt < 8) { BT = WqT; n0b = xt * 128; }
  else if (xt < 10) { BT = WkT; n0b = (xt - 8) * 128; }
  else { BT = WvT; n0b = (xt - 10) * 128; }
  float* C = g_part + (size_t)(z * 12 + xt) * MTOT * 128;
  gemm_body(x + (size_t)z * 1024, BT + (size_t)z * 1024, C,
            128, 1024, HID_N, m0, n0b, 0, 0, 1, (const float*)0);
}

// Combine split-K halves + epilogues -> qb/kb/vp
__global__ void qkv_combine_kernel() {
  const int xt = blockIdx.y;
  const int idx4 = blockIdx.x * 256 + threadIdx.x;   // 0..131071 (f4 within xt)
  const size_t off = (size_t)xt * MTOT * 128 + (size_t)idx4 * 4;
  float4 a = *(const float4*)(g_part + off);
  float4 b = *(const float4*)(g_part + (size_t)12 * MTOT * 128 + off);
  a.x += b.x; a.y += b.y; a.z += b.z; a.w += b.w;
  if (xt < 10) {
    a.x = rnd_tf32(tanhf(a.x));
    a.y = rnd_tf32(tanhf(a.y));
    a.z = rnd_tf32(tanhf(a.z));
    a.w = rnd_tf32(tanhf(a.w));
  } else {
    a.x = rnd_tf32(1.f / (1.f + __expf(-a.x)) - 0.5f);
    a.y = rnd_tf32(1.f / (1.f + __expf(-a.y)) - 0.5f);
    a.z = rnd_tf32(1.f / (1.f + __expf(-a.z)) - 0.5f);
    a.w = rnd_tf32(1.f / (1.f + __expf(-a.w)) - 0.5f);
  }
  const int row = idx4 >> 5;
  const int col = (idx4 & 31) * 4;
  if (xt < 8) {
    *(float4*)&g_qb[(size_t)row * (H_N * QKB_N) + xt * 128 + col] = a;
  } else if (xt < 10) {
    *(float4*)&g_kb[(size_t)row * (KV_N * QKB_N) + (xt - 8) * 128 + col] = a;
  } else {
    *(float4*)&g_vp[(size_t)row * (KV_N * VB_N) + (xt - 10) * 128 + col] = a;
  }
}

// Output projection: out = obd @ Wo + cvec
__global__ __launch_bounds__(256, 2)
void gemm_out(const float* __restrict__ obd, const float* __restrict__ WoT,
              float* __restrict__ out, const float* __restrict__ cvec) {
  const int n0 = blockIdx.x * 128;
  gemm_body(obd, WoT, out, HID_N, H_N * VB_N, H_N * VB_N,
            blockIdx.y * 128, n0, n0, 3, 0, cvec);
}

// ---------------------------------------------------------------------------
// Flash attention, tf32 mma.sync. Double-buffered cp.async K/V/mask tiles,
// per-warp causal skip, heavy q-tiles first. __launch_bounds__(256,2):
// cap regs at 128 so 2 CTAs/SM become resident (smem 102.5KB x2 <= 228KB).
// ---------------------------------------------------------------------------
#define KS_P 68
#define P_P 68
#define KVT_F (64 * KS_P)

__device__ __forceinline__ void attn_prefetch(
    uint32_t ksb, uint32_t vsb, int tid, int b, int kv, int k0) {
#pragma unroll
  for (int it = 0; it < 4; ++it) {
    int c = tid + it * 256;
    int r = c >> 4;
    int ch = c & 15;
    cp16(ksb + r * (KS_P * 4) + ch * 16,
         g_kb + (((size_t)b * S_N + k0 + r) * KV_N + kv) * QKB_N + ch * 4);
  }
#pragma unroll
  for (int it = 0; it < 4; ++it) {
    int c = tid + it * 256;
    int vc = c >> 4;
    int ch = c & 15;
    cp16(vsb + vc * (KS_P * 4) + ch * 16,
         g_vpT + ((size_t)b * (KV_N * VB_N) + kv * VB_N + vc) * S_N + k0 + ch * 4);
  }
}

__global__ __launch_bounds__(256, 2)
void attn_mma_kernel(const int* __restrict__ amask,
                     const float* __restrict__ emb0,
                     const float* __restrict__ emb1) {
  extern __shared__ float smn[];
  float* Ks  = smn;                       // [2][64][KS_P]
  float* Vst = Ks + 2 * KVT_F;            // [2][64][KS_P]
  float* Pw  = Vst + 2 * KVT_F;           // [8 warps][16][P_P]
  int*   Ms  = (int*)(Pw + 8 * 16 * P_P); // [2][64]

  const int qt = (int)gridDim.x - 1 - (int)blockIdx.x;  // heavy tiles first
  const int h  = blockIdx.y;
  const int b  = blockIdx.z;
  const int kv = h >> 2;
  const int tid = threadIdx.x;
  const int w = tid >> 5;
  const int lane = tid & 31;
  const int lg = lane >> 2;
  const int lt = lane & 3;
  const int q0 = qt * 128;
  const int r0 = q0 + w * 16 + lg;
  const int r1 = r0 + 8;
  const int qmax_w = q0 + w * 16 + 15;
  const int rA = lane & 15;
  const int kaddA = ((lane >> 4) << 2);
  const int rB = ((lane >> 4) << 3) + (lane & 7);
  const int kaddB = (((lane >> 3) & 1) << 2);
  const float EXSC = 0.022542110013890053f;  // log2(e)/64

  uint32_t aq[8][4];
  {
    const float* Q0 = g_qb + (((size_t)b * S_N + r0) * H_N + h) * QKB_N;
    const float* Q1 = g_qb + (((size_t)b * S_N + r1) * H_N + h) * QKB_N;
#pragma unroll
    for (int ks = 0; ks < 8; ++ks) {
      aq[ks][0] = __float_as_uint(Q0[ks * 8 + lt]);
      aq[ks][1] = __float_as_uint(Q1[ks * 8 + lt]);
      aq[ks][2] = __float_as_uint(Q0[ks * 8 + lt + 4]);
      aq[ks][3] = __float_as_uint(Q1[ks * 8 + lt + 4]);
    }
  }

  float acc[8][4];
#pragma unroll
  for (int nj = 0; nj < 8; ++nj) {
#pragma unroll
    for (int t = 0; t < 4; ++t) { acc[nj][t] = 0.f; }
  }
  float l0 = 0.f, l1 = 0.f;

  float* Pme = Pw + w * 16 * P_P;
  const uint32_t ks_u = smem_u32(Ks);
  const uint32_t vs_u = smem_u32(Vst);
  const uint32_t ms_u = smem_u32(Ms);

  const int nkt = 2 * qt + 2;

  attn_prefetch(ks_u, vs_u, tid, b, kv, 0);
  if (tid < 16) {
    cp16(ms_u + tid * 16, amask + (size_t)b * S_N + tid * 4);
  }
  cp_commit();

  for (int kt = 0; kt < nkt; ++kt) {
    const int bi = kt & 1;
    cp_waitg0();
    __syncthreads();
    if (kt + 1 < nkt) {
      const int ni = (kt + 1) & 1;
      attn_prefetch(ks_u + ni * (KVT_F * 4), vs_u + ni * (KVT_F * 4),
                    tid, b, kv, (kt + 1) * 64);
      if (tid < 16) {
        cp16(ms_u + ni * 256 + tid * 16, amask + (size_t)b * S_N + (kt + 1) * 64 + tid * 4);
      }
      cp_commit();
    }

    const int k0 = kt * 64;
    if (k0 > qmax_w) { continue; }

    const float* Ksb = Ks + bi * KVT_F;
    const float* Vsb = Vst + bi * KVT_F;
    const int* Msb = Ms + bi * 64;

    // ---- S = Q @ K^T ----
    float s[8][4];
#pragma unroll
    for (int nj = 0; nj < 8; ++nj) {
#pragma unroll
      for (int t = 0; t < 4; ++t) { s[nj][t] = 0.f; }
    }
#pragma unroll
    for (int ks = 0; ks < 8; ++ks) {
#pragma unroll
      for (int j = 0; j < 4; ++j) {
        uint32_t r[4];
        ldsm4(r, smem_u32(&Ksb[(j * 16 + rB) * KS_P + ks * 8 + kaddB]));
        mma_tf32(s[2 * j + 0], aq[ks], r + 0);
        mma_tf32(s[2 * j + 1], aq[ks], r + 2);
      }
    }

    // ---- probs = exp(s/64), masked -> 0 ----
    float rs0 = 0.f, rs1 = 0.f;
#pragma unroll
    for (int nj = 0; nj < 8; ++nj) {
      int c0i = nj * 8 + lt * 2;
      int kc0 = k0 + c0i;
      int kc1 = kc0 + 1;
      bool mk0 = Msb[c0i] != 0;
      bool mk1 = Msb[c0i + 1] != 0;
      float p00 = (kc0 <= r0 && mk0) ? exp2f(s[nj][0] * EXSC) : 0.f;
      float p01 = (kc1 <= r0 && mk1) ? exp2f(s[nj][1] * EXSC) : 0.f;
      float p10 = (kc0 <= r1 && mk0) ? exp2f(s[nj][2] * EXSC) : 0.f;
      float p11 = (kc1 <= r1 && mk1) ? exp2f(s[nj][3] * EXSC) : 0.f;
      rs0 += p00 + p01;
      rs1 += p10 + p11;
      float2 q2a = make_float2(p00, p01);
      float2 q2b = make_float2(p10, p11);
      *(float2*)&Pme[lg * P_P + nj * 8 + lt * 2] = q2a;
      *(float2*)&Pme[(lg + 8) * P_P + nj * 8 + lt * 2] = q2b;
    }
    rs0 += __shfl_xor_sync(0xffffffffu, rs0, 1);
    rs0 += __shfl_xor_sync(0xffffffffu, rs0, 2);
    rs1 += __shfl_xor_sync(0xffffffffu, rs1, 1);
    rs1 += __shfl_xor_sync(0xffffffffu, rs1, 2);
    l0 += rs0;
    l1 += rs1;
    __syncwarp();

    // ---- O += P @ V' ----
#pragma unroll
    for (int ks = 0; ks < 8; ++ks) {
      uint32_t pr[4];
      ldsm4(pr, smem_u32(&Pme[rA * P_P + ks * 8 + kaddA]));
      uint32_t hi[4];
      hi[0] = f2tf32(__uint_as_float(pr[0]));
      hi[1] = f2tf32(__uint_as_float(pr[1]));
      hi[2] = f2tf32(__uint_as_float(pr[2]));
      hi[3] = f2tf32(__uint_as_float(pr[3]));
#pragma unroll
      for (int j = 0; j < 4; ++j) {
        uint32_t r[4];
        ldsm4(r, smem_u32(&Vsb[(j * 16 + rB) * KS_P + ks * 8 + kaddB]));
        mma_tf32(acc[2 * j + 0], hi, r + 0);
        mma_tf32(acc[2 * j + 1], hi, r + 2);
      }
    }
  }

  // ---- epilogue: centered out-bits (rounded to tf32 for the next GEMM) ----
  float inv0 = 1.f / l0;
  float inv1 = 1.f / l1;
#pragma unroll
  for (int nj = 0; nj < 8; ++nj) {
    int vc = nj * 8 + lt * 2;
    float d0 = emb1[h * VB_N + vc] - emb0[h * VB_N + vc];
    float d1 = emb1[h * VB_N + vc + 1] - emb0[h * VB_N + vc + 1];
    float2 o0 = make_float2(rnd_tf32(acc[nj][0] * inv0 * d0),
                            rnd_tf32(acc[nj][1] * inv0 * d1));
    float2 o1 = make_float2(rnd_tf32(acc[nj][2] * inv1 * d0),
                            rnd_tf32(acc[nj][3] * inv1 * d1));
    *(float2*)&g_obd[(((size_t)b * S_N + r0) * H_N + h) * VB_N + vc] = o0;
    *(float2*)&g_obd[(((size_t)b * S_N + r1) * H_N + h) * VB_N + vc] = o1;
  }
}

// ---------------------------------------------------------------------------
extern "C" void kernel_launch(void* const* d_in, const int* in_sizes, int n_in,
                              void* d_out, int out_size) {
  const float* x  = (const float*)d_in[0];
  const int*   am = (const int*)d_in[1];
  const float* Wq = (const float*)d_in[2];
  const float* Wk = (const float*)d_in[3];
  const float* Wv = (const float*)d_in[4];
  const float* Wo = (const float*)d_in[5];
  const float* e0 = (const float*)d_in[6];
  const float* e1 = (const float*)d_in[7];
  float* out = (float*)d_out;

  float* obd;  float* cvec;
  float* wqt; float* wkt; float* wvt;  float* wot;
  cudaGetSymbolAddress((void**)&obd, g_obd);
  cudaGetSymbolAddress((void**)&cvec, g_cvec);
  cudaGetSymbolAddress((void**)&wqt, g_wqt);
  cudaGetSymbolAddress((void**)&wkt, g_wkt);
  cudaGetSymbolAddress((void**)&wvt, g_wvt);
  cudaGetSymbolAddress((void**)&wot, g_wot);

  const int M = MTOT;

  transpose_round_qkv_kernel<<<dim3(48, HID_N / 32), 256>>>(Wq, Wk, Wv);
  transpose_round_kernel<<<dim3(HID_N / 32, (H_N * VB_N) / 32), 256>>>(Wo, wot, H_N * VB_N, HID_N);
  cvec_kernel<<<HID_N / 64, 256>>>(e0, e1, Wo);

  cudaFuncSetAttribute(gemm_qkv_sk, cudaFuncAttributeMaxDynamicSharedMemorySize, GEMM_DSMEM);
  cudaFuncSetAttribute(gemm_out, cudaFuncAttributeMaxDynamicSharedMemorySize, GEMM_DSMEM);

  gemm_qkv_sk<<<dim3(12, M / 128, 2), 256, GEMM_DSMEM>>>(x, wqt, wkt, wvt);
  qkv_combine_kernel<<<dim3(M * 128 / (256 * 4), 12), 256>>>();

  transpose_v_kernel<<<dim3((KV_N * VB_N) / 32, S_N / 32, B_N), 256>>>();

  size_t asmem = (size_t)(2 * KVT_F + 2 * KVT_F + 8 * 16 * P_P) * sizeof(float)
               + 2 * 64 * sizeof(int);
  cudaFuncSetAttribute(attn_mma_kernel, cudaFuncAttributeMaxDynamicSharedMemorySize, (int)asmem);
  attn_mma_kernel<<<dim3(S_N / 128, H_N, B_N), 256, asmem>>>(am, e0, e1);

  gemm_out<<<dim3(HID_N / 128, M / 128), 256, GEMM_DSMEM>>>(obd, wot, out, cvec);
}